// round 7
// baseline (speedup 1.0000x reference)
#include <cuda_runtime.h>
#include <cuda_bf16.h>
#include <math.h>
#include <stdint.h>

#define BB 128
#define TT 1024
#define HH 512
#define GG 1536
#define NCTA 128

// ---------------- device scratch (no allocation) ----------------
__device__ float g_xp[(size_t)BB * TT * GG];
__device__ __nv_bfloat16 g_xhi[(size_t)BB * TT * 256];
__device__ __nv_bfloat16 g_xlo[(size_t)BB * TT * 256];
__device__ __nv_bfloat16 g_h1hi[(size_t)BB * TT * HH];
__device__ __nv_bfloat16 g_h1lo[(size_t)BB * TT * HH];
__device__ __nv_bfloat16 g_w0hi[GG * 256], g_w0lo[GG * 256];
__device__ __nv_bfloat16 g_w1hi[GG * HH],  g_w1lo[GG * HH];
__device__ __nv_bfloat16 g_whhhi[2][16 * 96 * 512];
__device__ __nv_bfloat16 g_whhlo[2][16 * 96 * 512];
__device__ __nv_bfloat16 g_hbhi[2][BB * HH];
__device__ __nv_bfloat16 g_hblo[2][BB * HH];
// per-CTA progress flags: [mg][ng][pad 128B]; monotonic across launches/replays
__device__ unsigned g_flag[8][16][32];

// ---------------- PTX helpers (baseline PTX only) ----------------
__device__ __forceinline__ uint32_t smem_u32(const void* p) {
    uint32_t a;
    asm("{ .reg .u64 t; cvta.to.shared.u64 t, %1; cvt.u32.u64 %0, t; }" : "=r"(a) : "l"(p));
    return a;
}

#define CP16(dst, src) \
    asm volatile("cp.async.cg.shared.global [%0], [%1], 16;" :: "r"(dst), "l"(src))
#define CPCOMMIT() asm volatile("cp.async.commit_group;")
#define CPWAIT0()  asm volatile("cp.async.wait_group 0;")
#define CPWAIT1()  asm volatile("cp.async.wait_group 1;")

#define LDSM4(r, a) \
    asm volatile("ldmatrix.sync.aligned.m8n8.x4.shared.b16 {%0,%1,%2,%3}, [%4];" \
        : "=r"((r)[0]), "=r"((r)[1]), "=r"((r)[2]), "=r"((r)[3]) : "r"(a))
#define LDSM2(r, a) \
    asm volatile("ldmatrix.sync.aligned.m8n8.x2.shared.b16 {%0,%1}, [%2];" \
        : "=r"((r)[0]), "=r"((r)[1]) : "r"(a))

#define MMA16816(c, a, b) \
    asm volatile("mma.sync.aligned.m16n8k16.row.col.f32.bf16.bf16.f32 " \
        "{%0,%1,%2,%3}, {%4,%5,%6,%7}, {%8,%9}, {%0,%1,%2,%3};" \
        : "+f"((c)[0]), "+f"((c)[1]), "+f"((c)[2]), "+f"((c)[3]) \
        : "r"((a)[0]), "r"((a)[1]), "r"((a)[2]), "r"((a)[3]), "r"((b)[0]), "r"((b)[1]))

__device__ __forceinline__ void relstore(unsigned* p, unsigned v) {
    asm volatile("st.release.gpu.u32 [%0], %1;" :: "l"(p), "r"(v) : "memory");
}
__device__ __forceinline__ unsigned acqload(unsigned* p) {
    unsigned v;
    asm volatile("ld.acquire.gpu.u32 %0, [%1];" : "=r"(v) : "l"(p) : "memory");
    return v;
}

// ---------------- conversions ----------------
__global__ void split_f32(const float* __restrict__ src, size_t n,
                          __nv_bfloat16* __restrict__ hi, __nv_bfloat16* __restrict__ lo) {
    size_t i = (size_t)blockIdx.x * blockDim.x + threadIdx.x;
    if (i < n) {
        float v = src[i];
        __nv_bfloat16 h = __float2bfloat16(v);
        hi[i] = h;
        lo[i] = __float2bfloat16(v - __bfloat162float(h));
    }
}

// reorder Whh [1536,512] -> [16 ng][96][512]
__global__ void split_whh(const float* __restrict__ W,
                          __nv_bfloat16* __restrict__ hi, __nv_bfloat16* __restrict__ lo) {
    int i = blockIdx.x * 256 + threadIdx.x;
    int k = i & 511;
    int ro = i >> 9;
    int ng = ro / 96, j = ro % 96;
    int g = j >> 5, jj = j & 31;
    float v = W[(size_t)(g * 512 + ng * 32 + jj) * 512 + k];
    __nv_bfloat16 h = __float2bfloat16(v);
    hi[i] = h;
    lo[i] = __float2bfloat16(v - __bfloat162float(h));
}

// ---------------- mma.sync GEMM, 3-stage cp.async pipeline, occ 2 ----------------
template <int K>
__global__ void __launch_bounds__(256, 2) gemm_mma(
    const __nv_bfloat16* __restrict__ Ahi, const __nv_bfloat16* __restrict__ Alo,
    const __nv_bfloat16* __restrict__ Bhi, const __nv_bfloat16* __restrict__ Blo,
    const float* __restrict__ bias, float* __restrict__ C)
{
    extern __shared__ char smx[];
    const uint32_t sb = smem_u32(smx);
    const int tid = threadIdx.x, w = tid >> 5, lane = tid & 31;
    const int wm = w >> 2, wn = w & 3;
    const int m0 = blockIdx.y * 128, n0 = blockIdx.x * 128;

    float c[4][4][4];
#pragma unroll
    for (int i = 0; i < 4; i++)
#pragma unroll
        for (int j = 0; j < 4; j++)
#pragma unroll
            for (int q = 0; q < 4; q++) c[i][j][q] = 0.f;

    const int a_r  = (lane & 7) + ((lane >> 3) & 1) * 8;
    const int a_co = lane >> 4;
    const int b_r  = lane & 7;
    const int b_co = (lane >> 3) & 1;

    const int KC = K / 64;
    const int NIT = 3 * KC;

    auto stage = [&](int it, int buf) {
        int p = it / KC;
        int kc = (it - p * KC) * 64;
        const __nv_bfloat16* Ap = (p == 1) ? Alo : Ahi;
        const __nv_bfloat16* Bp = (p == 2) ? Blo : Bhi;
#pragma unroll
        for (int j = 0; j < 4; j++) {
            int idx = tid + j * 256;
            int r = idx >> 3, cc = idx & 7;
            uint32_t off = (uint32_t)(r * 128 + ((cc ^ (r & 7)) << 4));
            CP16(sb + buf * 32768 + off, Ap + (size_t)(m0 + r) * K + kc + cc * 8);
            CP16(sb + buf * 32768 + 16384 + off, Bp + (size_t)(n0 + r) * K + kc + cc * 8);
        }
    };

    stage(0, 0); CPCOMMIT();
    stage(1, 1); CPCOMMIT();
    for (int it = 0; it < NIT; it++) {
        int buf = it % 3;
        CPWAIT1();
        __syncthreads();

        const uint32_t Ab = sb + buf * 32768 + (wm * 64) * 128;
        const uint32_t Bb = sb + buf * 32768 + 16384 + (wn * 32) * 128;
#pragma unroll
        for (int kk = 0; kk < 4; kk++) {
            uint32_t a[4][4];
            uint32_t asw = (uint32_t)(((2 * kk + a_co) ^ (a_r & 7)) << 4);
#pragma unroll
            for (int mt = 0; mt < 4; mt++)
                LDSM4(a[mt], Ab + (mt * 16 + a_r) * 128 + asw);
            uint32_t bsw = (uint32_t)(((2 * kk + b_co) ^ (b_r & 7)) << 4);
#pragma unroll
            for (int nt = 0; nt < 4; nt++) {
                uint32_t b[2];
                LDSM2(b, Bb + (nt * 8 + b_r) * 128 + bsw);
#pragma unroll
                for (int mt = 0; mt < 4; mt++)
                    MMA16816(c[mt][nt], a[mt], b);
            }
        }
        if (it + 2 < NIT) stage(it + 2, (it + 2) % 3);
        CPCOMMIT();
    }

#pragma unroll
    for (int nt = 0; nt < 4; nt++) {
        int col = n0 + wn * 32 + nt * 8 + (lane & 3) * 2;
        float2 bv = *(const float2*)&bias[col];
#pragma unroll
        for (int mt = 0; mt < 4; mt++) {
            int row = m0 + wm * 64 + mt * 16 + (lane >> 2);
            float2 v0 = { c[mt][nt][0] + bv.x, c[mt][nt][1] + bv.y };
            float2 v1 = { c[mt][nt][2] + bv.x, c[mt][nt][3] + bv.y };
            *(float2*)&C[(size_t)row * GG + col] = v0;
            *(float2*)&C[(size_t)(row + 8) * GG + col] = v1;
        }
    }
}

// ---------------- persistent mma.sync GRU layer ----------------
// dred overlays the W_HI smem region (dead after the register hoist), so no
// sync is needed between the MMA loop and the partial-sum stores.
__global__ void __launch_bounds__(256, 1) gru_mma(
    const float* __restrict__ xp,
    const __nv_bfloat16* __restrict__ Whi_g, const __nv_bfloat16* __restrict__ Wlo_g,
    const float* __restrict__ bhh,
    __nv_bfloat16* __restrict__ seqhi, __nv_bfloat16* __restrict__ seqlo)
{
    extern __shared__ char smx[];
    const uint32_t sb = smem_u32(smx);
    float* sbias = (float*)smx;                    // 96 floats
    const uint32_t W_HI = 512;
    const uint32_t W_LO = 512 + 98304;
    const uint32_t A_HI = 512 + 196608;
    const uint32_t A_LO = A_HI + 16384;
    float* dred = (float*)(smx + W_HI);            // overlays W_HI (dead after hoist)

    const int tid = threadIdx.x, w = tid >> 5, lane = tid & 31;
    const int nq = w & 3, kh = w >> 2;
    const int ng = blockIdx.x & 15, mg = blockIdx.x >> 4;

    const unsigned base = g_flag[mg][ng][0];       // stable between launches

    // persistent W slice, swizzled
    const __nv_bfloat16* wh = Whi_g + (size_t)ng * 96 * 512;
    const __nv_bfloat16* wl = Wlo_g + (size_t)ng * 96 * 512;
    for (int idx = tid; idx < 6144; idx += 256) {
        int r = idx >> 6, cc = idx & 63;
        uint32_t off = (uint32_t)(r * 1024 + ((cc ^ (r & 7)) << 4));
        *(uint4*)(smx + W_HI + off) = *(const uint4*)(wh + r * 512 + cc * 8);
        *(uint4*)(smx + W_LO + off) = *(const uint4*)(wl + r * 512 + cc * 8);
    }
    if (tid < 96) sbias[tid] = bhh[(tid >> 5) * 512 + ng * 32 + (tid & 31)];

    // zero owned region of initial state
    if (tid < 128) {
        int b = mg * 16 + (tid >> 3);
        int cc = ng * 32 + (tid & 7) * 4;
        uint2 zb = {0u, 0u};
        *(uint2*)&g_hbhi[0][b * 512 + cc] = zb;
        *(uint2*)&g_hblo[0][b * 512 + cc] = zb;
    }
    __syncthreads();

    const int a_r  = (lane & 7) + ((lane >> 3) & 1) * 8;
    const int a_co = lane >> 4;
    const int b_r  = lane & 7;
    const int b_co = (lane >> 3) & 1;
    const uint32_t AbHi = sb + A_HI + a_r * 1024;
    const uint32_t AbLo = sb + A_LO + a_r * 1024;
    uint32_t BbHi[3], BbLo[3];
#pragma unroll
    for (int f = 0; f < 3; f++) {
        int n = nq * 24 + f * 8 + b_r;
        BbHi[f] = sb + W_HI + n * 1024;
        BbLo[f] = sb + W_LO + n * 1024;
    }

    // hoist W-hi fragments into registers (loop-invariant over all 1024 steps)
    uint32_t bhr[3][16][2];
#pragma unroll
    for (int kk0 = 0; kk0 < 16; kk0++) {
        int kk = kh * 16 + kk0;
        uint32_t bsw = (uint32_t)(((2 * kk + b_co) ^ (b_r & 7)) << 4);
#pragma unroll
        for (int f = 0; f < 3; f++)
            LDSM2(bhr[f][kk0], BbHi[f] + bsw);
    }
    __syncthreads();    // hoist reads of W_HI done before dred may overlay it

    // init-done flag (release: makes zero-init visible to group)
    if (tid == 0) relstore(&g_flag[mg][ng][0], base + 1);

    // epilogue/prefetch thread mapping
    const int b0  = tid >> 5;
    const int cc0 = tid & 31;
    const int bg0 = mg * 16 + b0;
    const int bg1 = bg0 + 8;
    const int hc0 = ng * 32 + cc0;
    const float* xpp0 = xp + (size_t)bg0 * TT * GG + hc0;
    const float* xpp1 = xp + (size_t)bg1 * TT * GG + hc0;

    for (int t = 0; t < TT; t++) {
        const int cur = t & 1, nxt = cur ^ 1;

        // prefetch xp + own hold (no inter-CTA dependency) before the flag wait
        const size_t to = (size_t)t * GG;
        float pxr0 = __ldg(xpp0 + to),        pxr1 = __ldg(xpp1 + to);
        float pxz0 = __ldg(xpp0 + to + 512),  pxz1 = __ldg(xpp1 + to + 512);
        float pxn0 = __ldg(xpp0 + to + 1024), pxn1 = __ldg(xpp1 + to + 1024);
        float phold0 = __bfloat162float(g_hbhi[cur][bg0 * 512 + hc0])
                     + __bfloat162float(g_hblo[cur][bg0 * 512 + hc0]);
        float phold1 = __bfloat162float(g_hbhi[cur][bg1 * 512 + hc0])
                     + __bfloat162float(g_hblo[cur][bg1 * 512 + hc0]);

        // wait for all producers of h[cur]
        if (tid < 16) {
            const unsigned tgt = base + 1 + (unsigned)t;
            while ((int)(acqload(&g_flag[mg][tid][0]) - tgt) < 0) { }
        }
        __syncthreads();

        // stage h tile (16 rows x 512, hi+lo)
        const __nv_bfloat16* hh = &g_hbhi[cur][(size_t)mg * 16 * 512];
        const __nv_bfloat16* hl = &g_hblo[cur][(size_t)mg * 16 * 512];
#pragma unroll
        for (int j = 0; j < 4; j++) {
            int idx = tid + j * 256;
            int r = idx >> 6, cc = idx & 63;
            uint32_t off = (uint32_t)(r * 1024 + ((cc ^ (r & 7)) << 4));
            CP16(sb + A_HI + off, hh + r * 512 + cc * 8);
            CP16(sb + A_LO + off, hl + r * 512 + cc * 8);
        }
        CPCOMMIT(); CPWAIT0();
        __syncthreads();

        float acc[3][4];
#pragma unroll
        for (int f = 0; f < 3; f++)
#pragma unroll
            for (int q = 0; q < 4; q++) acc[f][q] = 0.f;

#pragma unroll
        for (int kk0 = 0; kk0 < 16; kk0++) {
            int kk = kh * 16 + kk0;
            uint32_t ahi[4], alo[4];
            uint32_t asw = (uint32_t)(((2 * kk + a_co) ^ (a_r & 7)) << 4);
            LDSM4(ahi, AbHi + asw);
            LDSM4(alo, AbLo + asw);
            uint32_t bsw = (uint32_t)(((2 * kk + b_co) ^ (b_r & 7)) << 4);
#pragma unroll
            for (int f = 0; f < 3; f++) {
                uint32_t bl[2];
                LDSM2(bl, BbLo[f] + bsw);
                MMA16816(acc[f], ahi, bhr[f][kk0]);
                MMA16816(acc[f], alo, bhr[f][kk0]);
                MMA16816(acc[f], ahi, bl);
            }
        }
        // no sync needed: dred (W_HI region) is disjoint from A/W_LO LDSM reads

#pragma unroll
        for (int f = 0; f < 3; f++) {
            int colc = nq * 24 + f * 8 + (lane & 3) * 2;
            int br = lane >> 2;
            float* p0 = &dred[(kh * 16 + br) * 100 + colc];
            float* p1 = &dred[(kh * 16 + br + 8) * 100 + colc];
            p0[0] = acc[f][0]; p0[1] = acc[f][1];
            p1[0] = acc[f][2]; p1[1] = acc[f][3];
        }
        __syncthreads();

        // fused gate epilogue; keep results in regs, write state, release, then seq
        __nv_bfloat16 rhb[2], rlb[2];
#pragma unroll
        for (int pp = 0; pp < 2; pp++) {
            int b = b0 + pp * 8;
            float Dr = dred[b * 100 + cc0]      + dred[(16 + b) * 100 + cc0];
            float Dz = dred[b * 100 + 32 + cc0] + dred[(16 + b) * 100 + 32 + cc0];
            float Dn = dred[b * 100 + 64 + cc0] + dred[(16 + b) * 100 + 64 + cc0];
            float xr = pp ? pxr1 : pxr0;
            float xz = pp ? pxz1 : pxz0;
            float xn = pp ? pxn1 : pxn0;
            float hold = pp ? phold1 : phold0;
            int bg = pp ? bg1 : bg0;
            float r = __fdividef(1.f, 1.f + __expf(-(xr + Dr + sbias[cc0])));
            float z = __fdividef(1.f, 1.f + __expf(-(xz + Dz + sbias[32 + cc0])));
            float pre = xn + r * (Dn + sbias[64 + cc0]);
            float e2 = __expf(2.f * pre);
            float n = 1.f - __fdividef(2.f, e2 + 1.f);
            float hv = (1.f - z) * n + z * hold;
            __nv_bfloat16 hb = __float2bfloat16(hv);
            float lo = hv - __bfloat162float(hb);
            __nv_bfloat16 lb = __float2bfloat16(lo);
            g_hbhi[nxt][bg * 512 + hc0] = hb;
            g_hblo[nxt][bg * 512 + hc0] = lb;
            rhb[pp] = hb; rlb[pp] = lb;
        }
        __syncthreads();    // h writes done before release
        if (tid == 0) relstore(&g_flag[mg][ng][0], base + 2 + (unsigned)t);

        if (seqhi) {        // history writes off the critical path
#pragma unroll
            for (int pp = 0; pp < 2; pp++) {
                int bg = pp ? bg1 : bg0;
                size_t so = ((size_t)bg * TT + t) * HH + hc0;
                seqhi[so] = rhb[pp];
                seqlo[so] = rlb[pp];
            }
        }
    }
}

// ---------------- final linear ----------------
__global__ void final_linear(const float* __restrict__ Wl, const float* __restrict__ bl,
                             float* __restrict__ out)
{
    __shared__ float ssum[4];
    int b = blockIdx.x, tid = threadIdx.x;
    float s = 0.f;
    for (int k = tid; k < 512; k += 128) {
        float hv = __bfloat162float(g_hbhi[0][b * 512 + k])
                 + __bfloat162float(g_hblo[0][b * 512 + k]);
        s += hv * Wl[k];
    }
#pragma unroll
    for (int o = 16; o > 0; o >>= 1) s += __shfl_down_sync(0xffffffffu, s, o);
    if ((tid & 31) == 0) ssum[tid >> 5] = s;
    __syncthreads();
    if (tid == 0) out[b] = ssum[0] + ssum[1] + ssum[2] + ssum[3] + bl[0];
}

// ---------------- launch ----------------
extern "C" void kernel_launch(void* const* d_in, const int* in_sizes, int n_in,
                              void* d_out, int out_size)
{
    const float* x    = (const float*)d_in[0];
    const float* Wih0 = (const float*)d_in[1];
    const float* Whh0 = (const float*)d_in[2];
    const float* bih0 = (const float*)d_in[3];
    const float* bhh0 = (const float*)d_in[4];
    const float* Wih1 = (const float*)d_in[5];
    const float* Whh1 = (const float*)d_in[6];
    const float* bih1 = (const float*)d_in[7];
    const float* bhh1 = (const float*)d_in[8];
    const float* Wlin = (const float*)d_in[9];
    const float* blin = (const float*)d_in[10];
    float* out = (float*)d_out;

    float* xp;
    __nv_bfloat16 *xhi, *xlo, *h1hi, *h1lo, *w0hi, *w0lo, *w1hi, *w1lo, *whhhi, *whhlo;
    cudaGetSymbolAddress((void**)&xp, g_xp);
    cudaGetSymbolAddress((void**)&xhi, g_xhi);
    cudaGetSymbolAddress((void**)&xlo, g_xlo);
    cudaGetSymbolAddress((void**)&h1hi, g_h1hi);
    cudaGetSymbolAddress((void**)&h1lo, g_h1lo);
    cudaGetSymbolAddress((void**)&w0hi, g_w0hi);
    cudaGetSymbolAddress((void**)&w0lo, g_w0lo);
    cudaGetSymbolAddress((void**)&w1hi, g_w1hi);
    cudaGetSymbolAddress((void**)&w1lo, g_w1lo);
    cudaGetSymbolAddress((void**)&whhhi, g_whhhi);
    cudaGetSymbolAddress((void**)&whhlo, g_whhlo);
    const size_t WHH_SZ = 16 * 96 * 512;

    const int GEMM_SMEM = 3 * 32768;
    const int GRU_SMEM  = 512 + 2 * 98304 + 2 * 16384;
    cudaFuncSetAttribute(gemm_mma<256>, cudaFuncAttributeMaxDynamicSharedMemorySize, GEMM_SMEM);
    cudaFuncSetAttribute(gemm_mma<512>, cudaFuncAttributeMaxDynamicSharedMemorySize, GEMM_SMEM);
    cudaFuncSetAttribute(gru_mma, cudaFuncAttributeMaxDynamicSharedMemorySize, GRU_SMEM);

    {
        size_t n = (size_t)BB * TT * 256;
        split_f32<<<(unsigned)((n + 255) / 256), 256>>>(x, n, xhi, xlo);
    }
    split_f32<<<(GG * 256 + 255) / 256, 256>>>(Wih0, (size_t)GG * 256, w0hi, w0lo);
    split_f32<<<(GG * 512 + 255) / 256, 256>>>(Wih1, (size_t)GG * 512, w1hi, w1lo);
    split_whh<<<3072, 256>>>(Whh0, whhhi, whhlo);
    split_whh<<<3072, 256>>>(Whh1, whhhi + WHH_SZ, whhlo + WHH_SZ);

    dim3 gg(GG / 128, (BB * TT) / 128);

    gemm_mma<256><<<gg, 256, GEMM_SMEM>>>(xhi, xlo, w0hi, w0lo, bih0, xp);
    gru_mma<<<NCTA, 256, GRU_SMEM>>>(xp, whhhi, whhlo, bhh0, h1hi, h1lo);
    gemm_mma<512><<<gg, 256, GEMM_SMEM>>>(h1hi, h1lo, w1hi, w1lo, bih1, xp);
    gru_mma<<<NCTA, 256, GRU_SMEM>>>(xp, whhhi + WHH_SZ, whhlo + WHH_SZ, bhh1, nullptr, nullptr);
    final_linear<<<BB, 128>>>(Wlin, blin, out);
}

// round 8
// speedup vs baseline: 1.1388x; 1.1388x over previous
#include <cuda_runtime.h>
#include <cuda_bf16.h>
#include <math.h>
#include <stdint.h>

#define BB 128
#define TT 1024
#define HH 512
#define GG 1536
#define NCTA 128

// ---------------- device scratch (no allocation) ----------------
__device__ float g_xp[(size_t)BB * TT * GG];
__device__ __nv_bfloat16 g_xhi[(size_t)BB * TT * 256];
__device__ __nv_bfloat16 g_xlo[(size_t)BB * TT * 256];
__device__ __nv_bfloat16 g_h1hi[(size_t)BB * TT * HH];
__device__ __nv_bfloat16 g_h1lo[(size_t)BB * TT * HH];
__device__ __nv_bfloat16 g_w0hi[GG * 256], g_w0lo[GG * 256];
__device__ __nv_bfloat16 g_w1hi[GG * HH],  g_w1lo[GG * HH];
__device__ __nv_bfloat16 g_whhhi[2][16 * 96 * 512];
__device__ __nv_bfloat16 g_whhlo[2][16 * 96 * 512];
__device__ __nv_bfloat16 g_hbhi[2][BB * HH];
__device__ __nv_bfloat16 g_hblo[2][BB * HH];
// per-CTA progress flags: [mg][ng][pad 128B]; monotonic across launches/replays
__device__ unsigned g_flag[8][16][32];

// ---------------- PTX helpers (baseline PTX only) ----------------
__device__ __forceinline__ uint32_t smem_u32(const void* p) {
    uint32_t a;
    asm("{ .reg .u64 t; cvta.to.shared.u64 t, %1; cvt.u32.u64 %0, t; }" : "=r"(a) : "l"(p));
    return a;
}

#define CP16(dst, src) \
    asm volatile("cp.async.cg.shared.global [%0], [%1], 16;" :: "r"(dst), "l"(src))
#define CPCOMMIT() asm volatile("cp.async.commit_group;")
#define CPWAIT0()  asm volatile("cp.async.wait_group 0;")
#define CPWAIT1()  asm volatile("cp.async.wait_group 1;")

#define LDSM4(r, a) \
    asm volatile("ldmatrix.sync.aligned.m8n8.x4.shared.b16 {%0,%1,%2,%3}, [%4];" \
        : "=r"((r)[0]), "=r"((r)[1]), "=r"((r)[2]), "=r"((r)[3]) : "r"(a))
#define LDSM2(r, a) \
    asm volatile("ldmatrix.sync.aligned.m8n8.x2.shared.b16 {%0,%1}, [%2];" \
        : "=r"((r)[0]), "=r"((r)[1]) : "r"(a))

#define MMA16816(c, a, b) \
    asm volatile("mma.sync.aligned.m16n8k16.row.col.f32.bf16.bf16.f32 " \
        "{%0,%1,%2,%3}, {%4,%5,%6,%7}, {%8,%9}, {%0,%1,%2,%3};" \
        : "+f"((c)[0]), "+f"((c)[1]), "+f"((c)[2]), "+f"((c)[3]) \
        : "r"((a)[0]), "r"((a)[1]), "r"((a)[2]), "r"((a)[3]), "r"((b)[0]), "r"((b)[1]))

__device__ __forceinline__ void relstore(unsigned* p, unsigned v) {
    asm volatile("st.release.gpu.u32 [%0], %1;" :: "l"(p), "r"(v) : "memory");
}
__device__ __forceinline__ unsigned acqload(unsigned* p) {
    unsigned v;
    asm volatile("ld.acquire.gpu.u32 %0, [%1];" : "=r"(v) : "l"(p) : "memory");
    return v;
}

// ---------------- conversions ----------------
__global__ void split_f32(const float* __restrict__ src, size_t n,
                          __nv_bfloat16* __restrict__ hi, __nv_bfloat16* __restrict__ lo) {
    size_t i = (size_t)blockIdx.x * blockDim.x + threadIdx.x;
    if (i < n) {
        float v = src[i];
        __nv_bfloat16 h = __float2bfloat16(v);
        hi[i] = h;
        lo[i] = __float2bfloat16(v - __bfloat162float(h));
    }
}

// reorder Whh [1536,512] -> [16 ng][96][512]
__global__ void split_whh(const float* __restrict__ W,
                          __nv_bfloat16* __restrict__ hi, __nv_bfloat16* __restrict__ lo) {
    int i = blockIdx.x * 256 + threadIdx.x;
    int k = i & 511;
    int ro = i >> 9;
    int ng = ro / 96, j = ro % 96;
    int g = j >> 5, jj = j & 31;
    float v = W[(size_t)(g * 512 + ng * 32 + jj) * 512 + k];
    __nv_bfloat16 h = __float2bfloat16(v);
    hi[i] = h;
    lo[i] = __float2bfloat16(v - __bfloat162float(h));
}

// ---------------- mma.sync GEMM, 3-stage cp.async pipeline (round-6 config) ----------------
template <int K>
__global__ void __launch_bounds__(256) gemm_mma(
    const __nv_bfloat16* __restrict__ Ahi, const __nv_bfloat16* __restrict__ Alo,
    const __nv_bfloat16* __restrict__ Bhi, const __nv_bfloat16* __restrict__ Blo,
    const float* __restrict__ bias, float* __restrict__ C)
{
    extern __shared__ char smx[];
    const uint32_t sb = smem_u32(smx);
    const int tid = threadIdx.x, w = tid >> 5, lane = tid & 31;
    const int wm = w >> 2, wn = w & 3;
    const int m0 = blockIdx.y * 128, n0 = blockIdx.x * 128;

    float c[4][4][4];
#pragma unroll
    for (int i = 0; i < 4; i++)
#pragma unroll
        for (int j = 0; j < 4; j++)
#pragma unroll
            for (int q = 0; q < 4; q++) c[i][j][q] = 0.f;

    const int a_r  = (lane & 7) + ((lane >> 3) & 1) * 8;
    const int a_co = lane >> 4;
    const int b_r  = lane & 7;
    const int b_co = (lane >> 3) & 1;

    const int KC = K / 64;
    const int NIT = 3 * KC;

    auto stage = [&](int it, int buf) {
        int p = it / KC;
        int kc = (it - p * KC) * 64;
        const __nv_bfloat16* Ap = (p == 1) ? Alo : Ahi;
        const __nv_bfloat16* Bp = (p == 2) ? Blo : Bhi;
#pragma unroll
        for (int j = 0; j < 4; j++) {
            int idx = tid + j * 256;
            int r = idx >> 3, cc = idx & 7;
            uint32_t off = (uint32_t)(r * 128 + ((cc ^ (r & 7)) << 4));
            CP16(sb + buf * 32768 + off, Ap + (size_t)(m0 + r) * K + kc + cc * 8);
            CP16(sb + buf * 32768 + 16384 + off, Bp + (size_t)(n0 + r) * K + kc + cc * 8);
        }
    };

    stage(0, 0); CPCOMMIT();
    stage(1, 1); CPCOMMIT();
    for (int it = 0; it < NIT; it++) {
        int buf = it % 3;
        CPWAIT1();
        __syncthreads();

        const uint32_t Ab = sb + buf * 32768 + (wm * 64) * 128;
        const uint32_t Bb = sb + buf * 32768 + 16384 + (wn * 32) * 128;
#pragma unroll
        for (int kk = 0; kk < 4; kk++) {
            uint32_t a[4][4];
            uint32_t asw = (uint32_t)(((2 * kk + a_co) ^ (a_r & 7)) << 4);
#pragma unroll
            for (int mt = 0; mt < 4; mt++)
                LDSM4(a[mt], Ab + (mt * 16 + a_r) * 128 + asw);
            uint32_t bsw = (uint32_t)(((2 * kk + b_co) ^ (b_r & 7)) << 4);
#pragma unroll
            for (int nt = 0; nt < 4; nt++) {
                uint32_t b[2];
                LDSM2(b, Bb + (nt * 8 + b_r) * 128 + bsw);
#pragma unroll
                for (int mt = 0; mt < 4; mt++)
                    MMA16816(c[mt][nt], a[mt], b);
            }
        }
        if (it + 2 < NIT) stage(it + 2, (it + 2) % 3);
        CPCOMMIT();
    }

#pragma unroll
    for (int nt = 0; nt < 4; nt++) {
        int col = n0 + wn * 32 + nt * 8 + (lane & 3) * 2;
        float2 bv = *(const float2*)&bias[col];
#pragma unroll
        for (int mt = 0; mt < 4; mt++) {
            int row = m0 + wm * 64 + mt * 16 + (lane >> 2);
            float2 v0 = { c[mt][nt][0] + bv.x, c[mt][nt][1] + bv.y };
            float2 v1 = { c[mt][nt][2] + bv.x, c[mt][nt][3] + bv.y };
            *(float2*)&C[(size_t)row * GG + col] = v0;
            *(float2*)&C[(size_t)(row + 8) * GG + col] = v1;
        }
    }
}

// ---------------- persistent mma.sync GRU layer ----------------
// Per-thread producer poll: each thread's staged chunks (cc = tid&63) come from
// exactly one peer CTA ng' = cc>>2, so it acquire-polls only that flag and
// stages immediately — no CTA-wide barrier between wait and stage.
__global__ void __launch_bounds__(256, 1) gru_mma(
    const float* __restrict__ xp,
    const __nv_bfloat16* __restrict__ Whi_g, const __nv_bfloat16* __restrict__ Wlo_g,
    const float* __restrict__ bhh,
    __nv_bfloat16* __restrict__ seqhi, __nv_bfloat16* __restrict__ seqlo)
{
    extern __shared__ char smx[];
    const uint32_t sb = smem_u32(smx);
    float* sbias = (float*)smx;                    // 96 floats
    const uint32_t W_HI = 512;
    const uint32_t W_LO = 512 + 98304;
    const uint32_t A_HI = 512 + 196608;
    const uint32_t A_LO = A_HI + 16384;
    float* dred = (float*)(smx + W_HI);            // overlays W_HI (dead after hoist)

    const int tid = threadIdx.x, w = tid >> 5, lane = tid & 31;
    const int nq = w & 3, kh = w >> 2;
    const int ng = blockIdx.x & 15, mg = blockIdx.x >> 4;

    const unsigned base = g_flag[mg][ng][0];       // stable between launches

    // persistent W slice, swizzled
    const __nv_bfloat16* wh = Whi_g + (size_t)ng * 96 * 512;
    const __nv_bfloat16* wl = Wlo_g + (size_t)ng * 96 * 512;
    for (int idx = tid; idx < 6144; idx += 256) {
        int r = idx >> 6, cc = idx & 63;
        uint32_t off = (uint32_t)(r * 1024 + ((cc ^ (r & 7)) << 4));
        *(uint4*)(smx + W_HI + off) = *(const uint4*)(wh + r * 512 + cc * 8);
        *(uint4*)(smx + W_LO + off) = *(const uint4*)(wl + r * 512 + cc * 8);
    }
    if (tid < 96) sbias[tid] = bhh[(tid >> 5) * 512 + ng * 32 + (tid & 31)];

    // zero owned region of initial state
    if (tid < 128) {
        int b = mg * 16 + (tid >> 3);
        int cc = ng * 32 + (tid & 7) * 4;
        uint2 zb = {0u, 0u};
        *(uint2*)&g_hbhi[0][b * 512 + cc] = zb;
        *(uint2*)&g_hblo[0][b * 512 + cc] = zb;
    }
    __syncthreads();

    const int a_r  = (lane & 7) + ((lane >> 3) & 1) * 8;
    const int a_co = lane >> 4;
    const int b_r  = lane & 7;
    const int b_co = (lane >> 3) & 1;
    const uint32_t AbHi = sb + A_HI + a_r * 1024;
    const uint32_t AbLo = sb + A_LO + a_r * 1024;
    uint32_t BbHi[3], BbLo[3];
#pragma unroll
    for (int f = 0; f < 3; f++) {
        int n = nq * 24 + f * 8 + b_r;
        BbHi[f] = sb + W_HI + n * 1024;
        BbLo[f] = sb + W_LO + n * 1024;
    }

    // hoist W-hi fragments into registers (loop-invariant over all 1024 steps)
    uint32_t bhr[3][16][2];
#pragma unroll
    for (int kk0 = 0; kk0 < 16; kk0++) {
        int kk = kh * 16 + kk0;
        uint32_t bsw = (uint32_t)(((2 * kk + b_co) ^ (b_r & 7)) << 4);
#pragma unroll
        for (int f = 0; f < 3; f++)
            LDSM2(bhr[f][kk0], BbHi[f] + bsw);
    }
    __syncthreads();    // hoist reads of W_HI done before dred may overlay it

    // init-done flag (release: makes zero-init visible to group)
    if (tid == 0) relstore(&g_flag[mg][ng][0], base + 1);

    // staging mapping: chunk column group is constant per thread
    const int st_cc = tid & 63;                 // 8-col chunk index, same for all j
    unsigned* myflag = &g_flag[mg][st_cc >> 2][0];

    // epilogue/prefetch thread mapping
    const int b0  = tid >> 5;
    const int cc0 = tid & 31;
    const int bg0 = mg * 16 + b0;
    const int bg1 = bg0 + 8;
    const int hc0 = ng * 32 + cc0;
    const float* xpp0 = xp + (size_t)bg0 * TT * GG + hc0;
    const float* xpp1 = xp + (size_t)bg1 * TT * GG + hc0;

    for (int t = 0; t < TT; t++) {
        const int cur = t & 1, nxt = cur ^ 1;

        // prefetch xp + own hold (no inter-CTA dependency) before the flag wait
        const size_t to = (size_t)t * GG;
        float pxr0 = __ldg(xpp0 + to),        pxr1 = __ldg(xpp1 + to);
        float pxz0 = __ldg(xpp0 + to + 512),  pxz1 = __ldg(xpp1 + to + 512);
        float pxn0 = __ldg(xpp0 + to + 1024), pxn1 = __ldg(xpp1 + to + 1024);
        float phold0 = __bfloat162float(g_hbhi[cur][bg0 * 512 + hc0])
                     + __bfloat162float(g_hblo[cur][bg0 * 512 + hc0]);
        float phold1 = __bfloat162float(g_hbhi[cur][bg1 * 512 + hc0])
                     + __bfloat162float(g_hblo[cur][bg1 * 512 + hc0]);

        // per-thread wait for the single producer of this thread's chunks
        {
            const unsigned tgt = base + 1 + (unsigned)t;
            while ((int)(acqload(myflag) - tgt) < 0) { }
        }

        // stage h tile (16 rows x 512, hi+lo) — own chunks only, no pre-sync
        const __nv_bfloat16* hh = &g_hbhi[cur][(size_t)mg * 16 * 512];
        const __nv_bfloat16* hl = &g_hblo[cur][(size_t)mg * 16 * 512];
#pragma unroll
        for (int j = 0; j < 4; j++) {
            int idx = tid + j * 256;
            int r = idx >> 6, cc = idx & 63;
            uint32_t off = (uint32_t)(r * 1024 + ((cc ^ (r & 7)) << 4));
            CP16(sb + A_HI + off, hh + r * 512 + cc * 8);
            CP16(sb + A_LO + off, hl + r * 512 + cc * 8);
        }
        CPCOMMIT(); CPWAIT0();
        __syncthreads();

        float acc[3][4];
#pragma unroll
        for (int f = 0; f < 3; f++)
#pragma unroll
            for (int q = 0; q < 4; q++) acc[f][q] = 0.f;

#pragma unroll
        for (int kk0 = 0; kk0 < 16; kk0++) {
            int kk = kh * 16 + kk0;
            uint32_t ahi[4], alo[4];
            uint32_t asw = (uint32_t)(((2 * kk + a_co) ^ (a_r & 7)) << 4);
            LDSM4(ahi, AbHi + asw);
            LDSM4(alo, AbLo + asw);
            uint32_t bsw = (uint32_t)(((2 * kk + b_co) ^ (b_r & 7)) << 4);
#pragma unroll
            for (int f = 0; f < 3; f++) {
                uint32_t bl[2];
                LDSM2(bl, BbLo[f] + bsw);
                MMA16816(acc[f], ahi, bhr[f][kk0]);
                MMA16816(acc[f], alo, bhr[f][kk0]);
                MMA16816(acc[f], ahi, bl);
            }
        }
        // no sync needed: dred (W_HI region) is disjoint from A/W_LO LDSM reads

#pragma unroll
        for (int f = 0; f < 3; f++) {
            int colc = nq * 24 + f * 8 + (lane & 3) * 2;
            int br = lane >> 2;
            float* p0 = &dred[(kh * 16 + br) * 100 + colc];
            float* p1 = &dred[(kh * 16 + br + 8) * 100 + colc];
            p0[0] = acc[f][0]; p0[1] = acc[f][1];
            p1[0] = acc[f][2]; p1[1] = acc[f][3];
        }
        __syncthreads();

        // fused gate epilogue; keep results in regs, write state, release, then seq
        __nv_bfloat16 rhb[2], rlb[2];
#pragma unroll
        for (int pp = 0; pp < 2; pp++) {
            int b = b0 + pp * 8;
            float Dr = dred[b * 100 + cc0]      + dred[(16 + b) * 100 + cc0];
            float Dz = dred[b * 100 + 32 + cc0] + dred[(16 + b) * 100 + 32 + cc0];
            float Dn = dred[b * 100 + 64 + cc0] + dred[(16 + b) * 100 + 64 + cc0];
            float xr = pp ? pxr1 : pxr0;
            float xz = pp ? pxz1 : pxz0;
            float xn = pp ? pxn1 : pxn0;
            float hold = pp ? phold1 : phold0;
            int bg = pp ? bg1 : bg0;
            float r = __fdividef(1.f, 1.f + __expf(-(xr + Dr + sbias[cc0])));
            float z = __fdividef(1.f, 1.f + __expf(-(xz + Dz + sbias[32 + cc0])));
            float pre = xn + r * (Dn + sbias[64 + cc0]);
            float e2 = __expf(2.f * pre);
            float n = 1.f - __fdividef(2.f, e2 + 1.f);
            float hv = (1.f - z) * n + z * hold;
            __nv_bfloat16 hb = __float2bfloat16(hv);
            float lo = hv - __bfloat162float(hb);
            __nv_bfloat16 lb = __float2bfloat16(lo);
            g_hbhi[nxt][bg * 512 + hc0] = hb;
            g_hblo[nxt][bg * 512 + hc0] = lb;
            rhb[pp] = hb; rlb[pp] = lb;
        }
        __syncthreads();    // h writes done before release
        if (tid == 0) relstore(&g_flag[mg][ng][0], base + 2 + (unsigned)t);

        if (seqhi) {        // history writes off the critical path
#pragma unroll
            for (int pp = 0; pp < 2; pp++) {
                int bg = pp ? bg1 : bg0;
                size_t so = ((size_t)bg * TT + t) * HH + hc0;
                seqhi[so] = rhb[pp];
                seqlo[so] = rlb[pp];
            }
        }
    }
}

// ---------------- final linear ----------------
__global__ void final_linear(const float* __restrict__ Wl, const float* __restrict__ bl,
                             float* __restrict__ out)
{
    __shared__ float ssum[4];
    int b = blockIdx.x, tid = threadIdx.x;
    float s = 0.f;
    for (int k = tid; k < 512; k += 128) {
        float hv = __bfloat162float(g_hbhi[0][b * 512 + k])
                 + __bfloat162float(g_hblo[0][b * 512 + k]);
        s += hv * Wl[k];
    }
#pragma unroll
    for (int o = 16; o > 0; o >>= 1) s += __shfl_down_sync(0xffffffffu, s, o);
    if ((tid & 31) == 0) ssum[tid >> 5] = s;
    __syncthreads();
    if (tid == 0) out[b] = ssum[0] + ssum[1] + ssum[2] + ssum[3] + bl[0];
}

// ---------------- launch ----------------
extern "C" void kernel_launch(void* const* d_in, const int* in_sizes, int n_in,
                              void* d_out, int out_size)
{
    const float* x    = (const float*)d_in[0];
    const float* Wih0 = (const float*)d_in[1];
    const float* Whh0 = (const float*)d_in[2];
    const float* bih0 = (const float*)d_in[3];
    const float* bhh0 = (const float*)d_in[4];
    const float* Wih1 = (const float*)d_in[5];
    const float* Whh1 = (const float*)d_in[6];
    const float* bih1 = (const float*)d_in[7];
    const float* bhh1 = (const float*)d_in[8];
    const float* Wlin = (const float*)d_in[9];
    const float* blin = (const float*)d_in[10];
    float* out = (float*)d_out;

    float* xp;
    __nv_bfloat16 *xhi, *xlo, *h1hi, *h1lo, *w0hi, *w0lo, *w1hi, *w1lo, *whhhi, *whhlo;
    cudaGetSymbolAddress((void**)&xp, g_xp);
    cudaGetSymbolAddress((void**)&xhi, g_xhi);
    cudaGetSymbolAddress((void**)&xlo, g_xlo);
    cudaGetSymbolAddress((void**)&h1hi, g_h1hi);
    cudaGetSymbolAddress((void**)&h1lo, g_h1lo);
    cudaGetSymbolAddress((void**)&w0hi, g_w0hi);
    cudaGetSymbolAddress((void**)&w0lo, g_w0lo);
    cudaGetSymbolAddress((void**)&w1hi, g_w1hi);
    cudaGetSymbolAddress((void**)&w1lo, g_w1lo);
    cudaGetSymbolAddress((void**)&whhhi, g_whhhi);
    cudaGetSymbolAddress((void**)&whhlo, g_whhlo);
    const size_t WHH_SZ = 16 * 96 * 512;

    const int GEMM_SMEM = 3 * 32768;
    const int GRU_SMEM  = 512 + 2 * 98304 + 2 * 16384;
    cudaFuncSetAttribute(gemm_mma<256>, cudaFuncAttributeMaxDynamicSharedMemorySize, GEMM_SMEM);
    cudaFuncSetAttribute(gemm_mma<512>, cudaFuncAttributeMaxDynamicSharedMemorySize, GEMM_SMEM);
    cudaFuncSetAttribute(gru_mma, cudaFuncAttributeMaxDynamicSharedMemorySize, GRU_SMEM);

    {
        size_t n = (size_t)BB * TT * 256;
        split_f32<<<(unsigned)((n + 255) / 256), 256>>>(x, n, xhi, xlo);
    }
    split_f32<<<(GG * 256 + 255) / 256, 256>>>(Wih0, (size_t)GG * 256, w0hi, w0lo);
    split_f32<<<(GG * 512 + 255) / 256, 256>>>(Wih1, (size_t)GG * 512, w1hi, w1lo);
    split_whh<<<3072, 256>>>(Whh0, whhhi, whhlo);
    split_whh<<<3072, 256>>>(Whh1, whhhi + WHH_SZ, whhlo + WHH_SZ);

    dim3 gg(GG / 128, (BB * TT) / 128);

    gemm_mma<256><<<gg, 256, GEMM_SMEM>>>(xhi, xlo, w0hi, w0lo, bih0, xp);
    gru_mma<<<NCTA, 256, GRU_SMEM>>>(xp, whhhi, whhlo, bhh0, h1hi, h1lo);
    gemm_mma<512><<<gg, 256, GEMM_SMEM>>>(h1hi, h1lo, w1hi, w1lo, bih1, xp);
    gru_mma<<<NCTA, 256, GRU_SMEM>>>(xp, whhhi + WHH_SZ, whhlo + WHH_SZ, bhh1, nullptr, nullptr);
    final_linear<<<BB, 128>>>(Wlin, blin, out);
}

// round 9
// speedup vs baseline: 1.1716x; 1.0288x over previous
#include <cuda_runtime.h>
#include <cuda_bf16.h>
#include <math.h>
#include <stdint.h>

#define BB 128
#define TT 1024
#define HH 512
#define GG 1536
#define NCTA 128

// ---------------- device scratch (no allocation) ----------------
__device__ float g_xp[(size_t)BB * TT * GG];
__device__ __nv_bfloat16 g_xhi[(size_t)BB * TT * 256];
__device__ __nv_bfloat16 g_xlo[(size_t)BB * TT * 256];
__device__ __nv_bfloat16 g_h1hi[(size_t)BB * TT * HH];
__device__ __nv_bfloat16 g_h1lo[(size_t)BB * TT * HH];
__device__ __nv_bfloat16 g_w0hi[GG * 256], g_w0lo[GG * 256];
__device__ __nv_bfloat16 g_w1hi[GG * HH],  g_w1lo[GG * HH];
__device__ __nv_bfloat16 g_whhhi[2][16 * 96 * 512];
__device__ __nv_bfloat16 g_whhlo[2][16 * 96 * 512];
__device__ __nv_bfloat16 g_hbhi[2][BB * HH];
__device__ __nv_bfloat16 g_hblo[2][BB * HH];
// per-CTA progress flags: [mg][ng][pad 128B]; monotonic across launches/replays
__device__ unsigned g_flag[8][16][32];

// ---------------- PTX helpers (baseline PTX only) ----------------
__device__ __forceinline__ uint32_t smem_u32(const void* p) {
    uint32_t a;
    asm("{ .reg .u64 t; cvta.to.shared.u64 t, %1; cvt.u32.u64 %0, t; }" : "=r"(a) : "l"(p));
    return a;
}

#define CP16(dst, src) \
    asm volatile("cp.async.cg.shared.global [%0], [%1], 16;" :: "r"(dst), "l"(src))
#define CPCOMMIT() asm volatile("cp.async.commit_group;")
#define CPWAIT0()  asm volatile("cp.async.wait_group 0;")
#define CPWAIT1()  asm volatile("cp.async.wait_group 1;")

#define LDSM4(r, a) \
    asm volatile("ldmatrix.sync.aligned.m8n8.x4.shared.b16 {%0,%1,%2,%3}, [%4];" \
        : "=r"((r)[0]), "=r"((r)[1]), "=r"((r)[2]), "=r"((r)[3]) : "r"(a))
#define LDSM2(r, a) \
    asm volatile("ldmatrix.sync.aligned.m8n8.x2.shared.b16 {%0,%1}, [%2];" \
        : "=r"((r)[0]), "=r"((r)[1]) : "r"(a))

#define MMA16816(c, a, b) \
    asm volatile("mma.sync.aligned.m16n8k16.row.col.f32.bf16.bf16.f32 " \
        "{%0,%1,%2,%3}, {%4,%5,%6,%7}, {%8,%9}, {%0,%1,%2,%3};" \
        : "+f"((c)[0]), "+f"((c)[1]), "+f"((c)[2]), "+f"((c)[3]) \
        : "r"((a)[0]), "r"((a)[1]), "r"((a)[2]), "r"((a)[3]), "r"((b)[0]), "r"((b)[1]))

__device__ __forceinline__ void relstore(unsigned* p, unsigned v) {
    asm volatile("st.release.gpu.u32 [%0], %1;" :: "l"(p), "r"(v) : "memory");
}
__device__ __forceinline__ unsigned acqload(unsigned* p) {
    unsigned v;
    asm volatile("ld.acquire.gpu.u32 %0, [%1];" : "=r"(v) : "l"(p) : "memory");
    return v;
}

// ---------------- conversions ----------------
__global__ void split_f32(const float* __restrict__ src, size_t n,
                          __nv_bfloat16* __restrict__ hi, __nv_bfloat16* __restrict__ lo) {
    size_t i = (size_t)blockIdx.x * blockDim.x + threadIdx.x;
    if (i < n) {
        float v = src[i];
        __nv_bfloat16 h = __float2bfloat16(v);
        hi[i] = h;
        lo[i] = __float2bfloat16(v - __bfloat162float(h));
    }
}

// reorder Whh [1536,512] -> [16 ng][96][512]
__global__ void split_whh(const float* __restrict__ W,
                          __nv_bfloat16* __restrict__ hi, __nv_bfloat16* __restrict__ lo) {
    int i = blockIdx.x * 256 + threadIdx.x;
    int k = i & 511;
    int ro = i >> 9;
    int ng = ro / 96, j = ro % 96;
    int g = j >> 5, jj = j & 31;
    float v = W[(size_t)(g * 512 + ng * 32 + jj) * 512 + k];
    __nv_bfloat16 h = __float2bfloat16(v);
    hi[i] = h;
    lo[i] = __float2bfloat16(v - __bfloat162float(h));
}

// ---------------- mma.sync GEMM, 3-stage cp.async pipeline (round-6 config) ----------------
template <int K>
__global__ void __launch_bounds__(256) gemm_mma(
    const __nv_bfloat16* __restrict__ Ahi, const __nv_bfloat16* __restrict__ Alo,
    const __nv_bfloat16* __restrict__ Bhi, const __nv_bfloat16* __restrict__ Blo,
    const float* __restrict__ bias, float* __restrict__ C)
{
    extern __shared__ char smx[];
    const uint32_t sb = smem_u32(smx);
    const int tid = threadIdx.x, w = tid >> 5, lane = tid & 31;
    const int wm = w >> 2, wn = w & 3;
    const int m0 = blockIdx.y * 128, n0 = blockIdx.x * 128;

    float c[4][4][4];
#pragma unroll
    for (int i = 0; i < 4; i++)
#pragma unroll
        for (int j = 0; j < 4; j++)
#pragma unroll
            for (int q = 0; q < 4; q++) c[i][j][q] = 0.f;

    const int a_r  = (lane & 7) + ((lane >> 3) & 1) * 8;
    const int a_co = lane >> 4;
    const int b_r  = lane & 7;
    const int b_co = (lane >> 3) & 1;

    const int KC = K / 64;
    const int NIT = 3 * KC;

    auto stage = [&](int it, int buf) {
        int p = it / KC;
        int kc = (it - p * KC) * 64;
        const __nv_bfloat16* Ap = (p == 1) ? Alo : Ahi;
        const __nv_bfloat16* Bp = (p == 2) ? Blo : Bhi;
#pragma unroll
        for (int j = 0; j < 4; j++) {
            int idx = tid + j * 256;
            int r = idx >> 3, cc = idx & 7;
            uint32_t off = (uint32_t)(r * 128 + ((cc ^ (r & 7)) << 4));
            CP16(sb + buf * 32768 + off, Ap + (size_t)(m0 + r) * K + kc + cc * 8);
            CP16(sb + buf * 32768 + 16384 + off, Bp + (size_t)(n0 + r) * K + kc + cc * 8);
        }
    };

    stage(0, 0); CPCOMMIT();
    stage(1, 1); CPCOMMIT();
    for (int it = 0; it < NIT; it++) {
        int buf = it % 3;
        CPWAIT1();
        __syncthreads();

        const uint32_t Ab = sb + buf * 32768 + (wm * 64) * 128;
        const uint32_t Bb = sb + buf * 32768 + 16384 + (wn * 32) * 128;
#pragma unroll
        for (int kk = 0; kk < 4; kk++) {
            uint32_t a[4][4];
            uint32_t asw = (uint32_t)(((2 * kk + a_co) ^ (a_r & 7)) << 4);
#pragma unroll
            for (int mt = 0; mt < 4; mt++)
                LDSM4(a[mt], Ab + (mt * 16 + a_r) * 128 + asw);
            uint32_t bsw = (uint32_t)(((2 * kk + b_co) ^ (b_r & 7)) << 4);
#pragma unroll
            for (int nt = 0; nt < 4; nt++) {
                uint32_t b[2];
                LDSM2(b, Bb + (nt * 8 + b_r) * 128 + bsw);
#pragma unroll
                for (int mt = 0; mt < 4; mt++)
                    MMA16816(c[mt][nt], a[mt], b);
            }
        }
        if (it + 2 < NIT) stage(it + 2, (it + 2) % 3);
        CPCOMMIT();
    }

#pragma unroll
    for (int nt = 0; nt < 4; nt++) {
        int col = n0 + wn * 32 + nt * 8 + (lane & 3) * 2;
        float2 bv = *(const float2*)&bias[col];
#pragma unroll
        for (int mt = 0; mt < 4; mt++) {
            int row = m0 + wm * 64 + mt * 16 + (lane >> 2);
            float2 v0 = { c[mt][nt][0] + bv.x, c[mt][nt][1] + bv.y };
            float2 v1 = { c[mt][nt][2] + bv.x, c[mt][nt][3] + bv.y };
            *(float2*)&C[(size_t)row * GG + col] = v0;
            *(float2*)&C[(size_t)(row + 8) * GG + col] = v1;
        }
    }
}

// ---------------- persistent mma.sync GRU layer ----------------
// K-half decoupling: warps 0-3 stage+consume K[0,256), warps 4-7 K[256,512);
// each half syncs with a named barrier. W-lo fragments fetched with .x4
// ldmatrix covering two K-steps per instruction (b_m = lane>>3 selects the
// K-chunk of each 8x8 matrix).
__global__ void __launch_bounds__(256, 1) gru_mma(
    const float* __restrict__ xp,
    const __nv_bfloat16* __restrict__ Whi_g, const __nv_bfloat16* __restrict__ Wlo_g,
    const float* __restrict__ bhh,
    __nv_bfloat16* __restrict__ seqhi, __nv_bfloat16* __restrict__ seqlo)
{
    extern __shared__ char smx[];
    const uint32_t sb = smem_u32(smx);
    float* sbias = (float*)smx;                    // 96 floats
    const uint32_t W_HI = 512;
    const uint32_t W_LO = 512 + 98304;
    const uint32_t A_HI = 512 + 196608;
    const uint32_t A_LO = A_HI + 16384;
    float* dred = (float*)(smx + W_HI);            // overlays W_HI (dead after hoist)

    const int tid = threadIdx.x, w = tid >> 5, lane = tid & 31;
    const int nq = w & 3, kh = w >> 2;
    const int half = tid >> 7;                     // == kh for this warp layout
    const int ng = blockIdx.x & 15, mg = blockIdx.x >> 4;

    const unsigned base = g_flag[mg][ng][0];       // stable between launches

    // persistent W slice, swizzled
    const __nv_bfloat16* wh = Whi_g + (size_t)ng * 96 * 512;
    const __nv_bfloat16* wl = Wlo_g + (size_t)ng * 96 * 512;
    for (int idx = tid; idx < 6144; idx += 256) {
        int r = idx >> 6, cc = idx & 63;
        uint32_t off = (uint32_t)(r * 1024 + ((cc ^ (r & 7)) << 4));
        *(uint4*)(smx + W_HI + off) = *(const uint4*)(wh + r * 512 + cc * 8);
        *(uint4*)(smx + W_LO + off) = *(const uint4*)(wl + r * 512 + cc * 8);
    }
    if (tid < 96) sbias[tid] = bhh[(tid >> 5) * 512 + ng * 32 + (tid & 31)];

    // zero owned region of initial state
    if (tid < 128) {
        int b = mg * 16 + (tid >> 3);
        int cc = ng * 32 + (tid & 7) * 4;
        uint2 zb = {0u, 0u};
        *(uint2*)&g_hbhi[0][b * 512 + cc] = zb;
        *(uint2*)&g_hblo[0][b * 512 + cc] = zb;
    }
    __syncthreads();

    const int a_r  = (lane & 7) + ((lane >> 3) & 1) * 8;
    const int a_co = lane >> 4;
    const int b_r  = lane & 7;
    const int b_co = (lane >> 3) & 1;
    const int b_m  = lane >> 3;                    // 0..3: K-chunk within .x4 fetch
    const uint32_t AbHi = sb + A_HI + a_r * 1024;
    const uint32_t AbLo = sb + A_LO + a_r * 1024;
    uint32_t BbHi[3], BbLo[3];
#pragma unroll
    for (int f = 0; f < 3; f++) {
        int n = nq * 24 + f * 8 + b_r;
        BbHi[f] = sb + W_HI + n * 1024;
        BbLo[f] = sb + W_LO + n * 1024;
    }

    // hoist W-hi fragments into registers (loop-invariant over all 1024 steps)
    uint32_t bhr[3][16][2];
#pragma unroll
    for (int kk0 = 0; kk0 < 16; kk0++) {
        int kk = kh * 16 + kk0;
        uint32_t bsw = (uint32_t)(((2 * kk + b_co) ^ (b_r & 7)) << 4);
#pragma unroll
        for (int f = 0; f < 3; f++)
            LDSM2(bhr[f][kk0], BbHi[f] + bsw);
    }
    __syncthreads();    // hoist reads of W_HI done before dred may overlay it

    // init-done flag (release: makes zero-init visible to group)
    if (tid == 0) relstore(&g_flag[mg][ng][0], base + 1);

    // staging mapping: thread stages chunk cc = half*32 + (tid&31), rows via j
    unsigned* myflag = &g_flag[mg][(half * 32 + (tid & 31)) >> 2][0];

    // epilogue/prefetch thread mapping
    const int b0  = tid >> 5;
    const int cc0 = tid & 31;
    const int bg0 = mg * 16 + b0;
    const int bg1 = bg0 + 8;
    const int hc0 = ng * 32 + cc0;
    const float* xpp0 = xp + (size_t)bg0 * TT * GG + hc0;
    const float* xpp1 = xp + (size_t)bg1 * TT * GG + hc0;

    for (int t = 0; t < TT; t++) {
        const int cur = t & 1, nxt = cur ^ 1;

        // prefetch xp + own hold (no inter-CTA dependency) before the flag wait
        const size_t to = (size_t)t * GG;
        float pxr0 = __ldg(xpp0 + to),        pxr1 = __ldg(xpp1 + to);
        float pxz0 = __ldg(xpp0 + to + 512),  pxz1 = __ldg(xpp1 + to + 512);
        float pxn0 = __ldg(xpp0 + to + 1024), pxn1 = __ldg(xpp1 + to + 1024);
        float phold0 = __bfloat162float(g_hbhi[cur][bg0 * 512 + hc0])
                     + __bfloat162float(g_hblo[cur][bg0 * 512 + hc0]);
        float phold1 = __bfloat162float(g_hbhi[cur][bg1 * 512 + hc0])
                     + __bfloat162float(g_hblo[cur][bg1 * 512 + hc0]);

        // per-thread wait for the single producer of this thread's chunks
        {
            const unsigned tgt = base + 1 + (unsigned)t;
            while ((int)(acqload(myflag) - tgt) < 0) { }
        }

        // stage own K-half of the h tile (16 rows x 256 cols, hi+lo)
        const __nv_bfloat16* hh = &g_hbhi[cur][(size_t)mg * 16 * 512];
        const __nv_bfloat16* hl = &g_hblo[cur][(size_t)mg * 16 * 512];
#pragma unroll
        for (int j = 0; j < 4; j++) {
            int idx = (tid & 127) + j * 128;
            int r = idx >> 5;                     // 0..15
            int cc = half * 32 + (idx & 31);      // own half's chunk
            uint32_t off = (uint32_t)(r * 1024 + ((cc ^ (r & 7)) << 4));
            CP16(sb + A_HI + off, hh + r * 512 + cc * 8);
            CP16(sb + A_LO + off, hl + r * 512 + cc * 8);
        }
        CPCOMMIT(); CPWAIT0();
        asm volatile("bar.sync %0, 128;" :: "r"(1 + half) : "memory");

        float acc[3][4];
#pragma unroll
        for (int f = 0; f < 3; f++)
#pragma unroll
            for (int q = 0; q < 4; q++) acc[f][q] = 0.f;

#pragma unroll
        for (int kp = 0; kp < 8; kp++) {
            int kk = kh * 16 + kp * 2;            // two K-steps per iter
            uint32_t asw0 = (uint32_t)(((2 * kk + a_co) ^ (a_r & 7)) << 4);
            uint32_t asw1 = (uint32_t)(((2 * kk + 2 + a_co) ^ (a_r & 7)) << 4);
            uint32_t ahi0[4], alo0[4], ahi1[4], alo1[4];
            LDSM4(ahi0, AbHi + asw0);
            LDSM4(alo0, AbLo + asw0);
            LDSM4(ahi1, AbHi + asw1);
            LDSM4(alo1, AbLo + asw1);
            uint32_t bsw = (uint32_t)(((2 * kk + b_m) ^ (b_r & 7)) << 4);
#pragma unroll
            for (int f = 0; f < 3; f++) {
                uint32_t bl[4];
                LDSM4(bl, BbLo[f] + bsw);         // covers kk and kk+1
                MMA16816(acc[f], ahi0, bhr[f][kp * 2]);
                MMA16816(acc[f], alo0, bhr[f][kp * 2]);
                MMA16816(acc[f], ahi0, bl);
                MMA16816(acc[f], ahi1, bhr[f][kp * 2 + 1]);
                MMA16816(acc[f], alo1, bhr[f][kp * 2 + 1]);
                MMA16816(acc[f], ahi1, bl + 2);
            }
        }
        // no sync needed: dred (W_HI region) is disjoint from A/W_LO LDSM reads

#pragma unroll
        for (int f = 0; f < 3; f++) {
            int colc = nq * 24 + f * 8 + (lane & 3) * 2;
            int br = lane >> 2;
            float* p0 = &dred[(kh * 16 + br) * 100 + colc];
            float* p1 = &dred[(kh * 16 + br + 8) * 100 + colc];
            p0[0] = acc[f][0]; p0[1] = acc[f][1];
            p1[0] = acc[f][2]; p1[1] = acc[f][3];
        }
        __syncthreads();

        // fused gate epilogue; keep results in regs, write state, release, then seq
        __nv_bfloat16 rhb[2], rlb[2];
#pragma unroll
        for (int pp = 0; pp < 2; pp++) {
            int b = b0 + pp * 8;
            float Dr = dred[b * 100 + cc0]      + dred[(16 + b) * 100 + cc0];
            float Dz = dred[b * 100 + 32 + cc0] + dred[(16 + b) * 100 + 32 + cc0];
            float Dn = dred[b * 100 + 64 + cc0] + dred[(16 + b) * 100 + 64 + cc0];
            float xr = pp ? pxr1 : pxr0;
            float xz = pp ? pxz1 : pxz0;
            float xn = pp ? pxn1 : pxn0;
            float hold = pp ? phold1 : phold0;
            int bg = pp ? bg1 : bg0;
            float r = __fdividef(1.f, 1.f + __expf(-(xr + Dr + sbias[cc0])));
            float z = __fdividef(1.f, 1.f + __expf(-(xz + Dz + sbias[32 + cc0])));
            float pre = xn + r * (Dn + sbias[64 + cc0]);
            float e2 = __expf(2.f * pre);
            float n = 1.f - __fdividef(2.f, e2 + 1.f);
            float hv = (1.f - z) * n + z * hold;
            __nv_bfloat16 hb = __float2bfloat16(hv);
            float lo = hv - __bfloat162float(hb);
            __nv_bfloat16 lb = __float2bfloat16(lo);
            g_hbhi[nxt][bg * 512 + hc0] = hb;
            g_hblo[nxt][bg * 512 + hc0] = lb;
            rhb[pp] = hb; rlb[pp] = lb;
        }
        __syncthreads();    // h writes done before release
        if (tid == 0) relstore(&g_flag[mg][ng][0], base + 2 + (unsigned)t);

        if (seqhi) {        // history writes off the critical path
#pragma unroll
            for (int pp = 0; pp < 2; pp++) {
                int bg = pp ? bg1 : bg0;
                size_t so = ((size_t)bg * TT + t) * HH + hc0;
                seqhi[so] = rhb[pp];
                seqlo[so] = rlb[pp];
            }
        }
    }
}

// ---------------- final linear ----------------
__global__ void final_linear(const float* __restrict__ Wl, const float* __restrict__ bl,
                             float* __restrict__ out)
{
    __shared__ float ssum[4];
    int b = blockIdx.x, tid = threadIdx.x;
    float s = 0.f;
    for (int k = tid; k < 512; k += 128) {
        float hv = __bfloat162float(g_hbhi[0][b * 512 + k])
                 + __bfloat162float(g_hblo[0][b * 512 + k]);
        s += hv * Wl[k];
    }
#pragma unroll
    for (int o = 16; o > 0; o >>= 1) s += __shfl_down_sync(0xffffffffu, s, o);
    if ((tid & 31) == 0) ssum[tid >> 5] = s;
    __syncthreads();
    if (tid == 0) out[b] = ssum[0] + ssum[1] + ssum[2] + ssum[3] + bl[0];
}

// ---------------- launch ----------------
extern "C" void kernel_launch(void* const* d_in, const int* in_sizes, int n_in,
                              void* d_out, int out_size)
{
    const float* x    = (const float*)d_in[0];
    const float* Wih0 = (const float*)d_in[1];
    const float* Whh0 = (const float*)d_in[2];
    const float* bih0 = (const float*)d_in[3];
    const float* bhh0 = (const float*)d_in[4];
    const float* Wih1 = (const float*)d_in[5];
    const float* Whh1 = (const float*)d_in[6];
    const float* bih1 = (const float*)d_in[7];
    const float* bhh1 = (const float*)d_in[8];
    const float* Wlin = (const float*)d_in[9];
    const float* blin = (const float*)d_in[10];
    float* out = (float*)d_out;

    float* xp;
    __nv_bfloat16 *xhi, *xlo, *h1hi, *h1lo, *w0hi, *w0lo, *w1hi, *w1lo, *whhhi, *whhlo;
    cudaGetSymbolAddress((void**)&xp, g_xp);
    cudaGetSymbolAddress((void**)&xhi, g_xhi);
    cudaGetSymbolAddress((void**)&xlo, g_xlo);
    cudaGetSymbolAddress((void**)&h1hi, g_h1hi);
    cudaGetSymbolAddress((void**)&h1lo, g_h1lo);
    cudaGetSymbolAddress((void**)&w0hi, g_w0hi);
    cudaGetSymbolAddress((void**)&w0lo, g_w0lo);
    cudaGetSymbolAddress((void**)&w1hi, g_w1hi);
    cudaGetSymbolAddress((void**)&w1lo, g_w1lo);
    cudaGetSymbolAddress((void**)&whhhi, g_whhhi);
    cudaGetSymbolAddress((void**)&whhlo, g_whhlo);
    const size_t WHH_SZ = 16 * 96 * 512;

    const int GEMM_SMEM = 3 * 32768;
    const int GRU_SMEM  = 512 + 2 * 98304 + 2 * 16384;
    cudaFuncSetAttribute(gemm_mma<256>, cudaFuncAttributeMaxDynamicSharedMemorySize, GEMM_SMEM);
    cudaFuncSetAttribute(gemm_mma<512>, cudaFuncAttributeMaxDynamicSharedMemorySize, GEMM_SMEM);
    cudaFuncSetAttribute(gru_mma, cudaFuncAttributeMaxDynamicSharedMemorySize, GRU_SMEM);

    {
        size_t n = (size_t)BB * TT * 256;
        split_f32<<<(unsigned)((n + 255) / 256), 256>>>(x, n, xhi, xlo);
    }
    split_f32<<<(GG * 256 + 255) / 256, 256>>>(Wih0, (size_t)GG * 256, w0hi, w0lo);
    split_f32<<<(GG * 512 + 255) / 256, 256>>>(Wih1, (size_t)GG * 512, w1hi, w1lo);
    split_whh<<<3072, 256>>>(Whh0, whhhi, whhlo);
    split_whh<<<3072, 256>>>(Whh1, whhhi + WHH_SZ, whhlo + WHH_SZ);

    dim3 gg(GG / 128, (BB * TT) / 128);

    gemm_mma<256><<<gg, 256, GEMM_SMEM>>>(xhi, xlo, w0hi, w0lo, bih0, xp);
    gru_mma<<<NCTA, 256, GRU_SMEM>>>(xp, whhhi, whhlo, bhh0, h1hi, h1lo);
    gemm_mma<512><<<gg, 256, GEMM_SMEM>>>(h1hi, h1lo, w1hi, w1lo, bih1, xp);
    gru_mma<<<NCTA, 256, GRU_SMEM>>>(xp, whhhi + WHH_SZ, whhlo + WHH_SZ, bhh1, nullptr, nullptr);
    final_linear<<<BB, 128>>>(Wlin, blin, out);
}